// round 1
// baseline (speedup 1.0000x reference)
#include <cuda_runtime.h>
#include <cuda_bf16.h>

// ---------------------------------------------------------------------------
// Problem constants: B=2, L=2048, D=1024, H=16, hd=64
// ---------------------------------------------------------------------------
#define BATCH 2
#define SEQ   2048
#define DMODEL 1024
#define NHEAD 16
#define HDIM  64
#define MTOT  (BATCH * SEQ)          // 4096
#define SOFTMAX_SCALE 0.125f         // 1/sqrt(64)

// Scratch (device globals; no runtime allocation allowed)
__device__ float g_q[MTOT * DMODEL];
__device__ float g_k[MTOT * DMODEL];
__device__ float g_v[MTOT * DMODEL];
__device__ float g_ctx[MTOT * DMODEL];

// ---------------------------------------------------------------------------
// SGEMM: C = A @ B^T.  A: [M,K] row-major, B: [N,K] row-major.
// 128x128 tile, BK=8, 256 threads, 8x8 microtile.
// MODE 0: C[m*N + n]  (plain row-major)
// MODE 1: scatter to (B,H,L,hd):  m=(b,l), n=(h,dd) -> C[((b*H+h)*L+l)*HDIM+dd]
// ---------------------------------------------------------------------------
template <int MODE>
__global__ __launch_bounds__(256) void sgemm_nt(const float* __restrict__ A,
                                                const float* __restrict__ B,
                                                float* __restrict__ C,
                                                int M, int N, int K) {
    // padded stride 132 words -> conflict-free transposed stores
    __shared__ float As[8 * 132];
    __shared__ float Bs[8 * 132];

    const int tid = threadIdx.x;
    const int ty = tid >> 4;        // 0..15
    const int tx = tid & 15;        // 0..15
    const int bm = blockIdx.y * 128;
    const int bn = blockIdx.x * 128;

    const int lr = tid >> 1;        // 0..127 (row within tile)
    const int lc = (tid & 1) * 4;   // 0 or 4 (k offset)

    const float* Ag = A + (size_t)(bm + lr) * K + lc;
    const float* Bg = B + (size_t)(bn + lr) * K + lc;

    float acc[8][8];
#pragma unroll
    for (int i = 0; i < 8; i++)
#pragma unroll
        for (int j = 0; j < 8; j++) acc[i][j] = 0.0f;

    for (int k0 = 0; k0 < K; k0 += 8) {
        float4 av = *reinterpret_cast<const float4*>(Ag + k0);
        float4 bv = *reinterpret_cast<const float4*>(Bg + k0);
        As[(lc + 0) * 132 + lr] = av.x;
        As[(lc + 1) * 132 + lr] = av.y;
        As[(lc + 2) * 132 + lr] = av.z;
        As[(lc + 3) * 132 + lr] = av.w;
        Bs[(lc + 0) * 132 + lr] = bv.x;
        Bs[(lc + 1) * 132 + lr] = bv.y;
        Bs[(lc + 2) * 132 + lr] = bv.z;
        Bs[(lc + 3) * 132 + lr] = bv.w;
        __syncthreads();

#pragma unroll
        for (int kk = 0; kk < 8; kk++) {
            float4 a0 = *reinterpret_cast<const float4*>(&As[kk * 132 + ty * 4]);
            float4 a1 = *reinterpret_cast<const float4*>(&As[kk * 132 + 64 + ty * 4]);
            float4 b0 = *reinterpret_cast<const float4*>(&Bs[kk * 132 + tx * 4]);
            float4 b1 = *reinterpret_cast<const float4*>(&Bs[kk * 132 + 64 + tx * 4]);
            float ar[8] = {a0.x, a0.y, a0.z, a0.w, a1.x, a1.y, a1.z, a1.w};
            float br[8] = {b0.x, b0.y, b0.z, b0.w, b1.x, b1.y, b1.z, b1.w};
#pragma unroll
            for (int i = 0; i < 8; i++)
#pragma unroll
                for (int j = 0; j < 8; j++) acc[i][j] = fmaf(ar[i], br[j], acc[i][j]);
        }
        __syncthreads();
    }

#pragma unroll
    for (int i = 0; i < 8; i++) {
        int r = bm + ((i < 4) ? (ty * 4 + i) : (64 + ty * 4 + i - 4));
#pragma unroll
        for (int j = 0; j < 8; j++) {
            int c = bn + ((j < 4) ? (tx * 4 + j) : (64 + tx * 4 + j - 4));
            if (MODE == 0) {
                C[(size_t)r * N + c] = acc[i][j];
            } else {
                int b = r >> 11;          // /SEQ
                int l = r & (SEQ - 1);
                int h = c >> 6;           // /HDIM
                int dd = c & (HDIM - 1);
                C[(((size_t)(b * NHEAD + h) * SEQ) + l) * HDIM + dd] = acc[i][j];
            }
        }
    }
}

// ---------------------------------------------------------------------------
// Flash attention (fp32, causal). Q/K/V in (B,H,L,hd) layout.
// Per CTA: one (b,h) and a 64-query block. 256 threads.
// BQ=64, BK=32. Thread (ty,tx): rows 4*ty+i (i<4), cols/dims tx+16*j.
// ---------------------------------------------------------------------------
#define AT_QSTR 68
#define AT_SSTR 36

__global__ __launch_bounds__(256) void flash_attn(const float* __restrict__ Q,
                                                  const float* __restrict__ K,
                                                  const float* __restrict__ V,
                                                  float* __restrict__ ctx) {
    __shared__ float Qs[64 * AT_QSTR];
    __shared__ float Ks[32 * AT_QSTR];
    __shared__ float Vs[32 * AT_QSTR];
    __shared__ float Ss[64 * AT_SSTR];

    const int tid = threadIdx.x;
    const int ty = tid >> 4;
    const int tx = tid & 15;
    const int bh = blockIdx.y;              // b*NHEAD + h
    const int q0 = blockIdx.x * 64;

    const float* Qg = Q + ((size_t)bh * SEQ + q0) * HDIM;
    const float* Kg = K + (size_t)bh * SEQ * HDIM;
    const float* Vg = V + (size_t)bh * SEQ * HDIM;

    // Load Q tile (64x64) with softmax scale folded in
#pragma unroll
    for (int it = 0; it < 4; it++) {
        int fi = tid + it * 256;
        int r = fi >> 4;
        int c = (fi & 15) * 4;
        float4 v = *reinterpret_cast<const float4*>(Qg + r * HDIM + c);
        float4 w = make_float4(v.x * SOFTMAX_SCALE, v.y * SOFTMAX_SCALE,
                               v.z * SOFTMAX_SCALE, v.w * SOFTMAX_SCALE);
        *reinterpret_cast<float4*>(&Qs[r * AT_QSTR + c]) = w;
    }

    float m_i[4], l_i[4], o[4][4];
#pragma unroll
    for (int i = 0; i < 4; i++) {
        m_i[i] = -1e30f;
        l_i[i] = 0.0f;
#pragma unroll
        for (int j = 0; j < 4; j++) o[i][j] = 0.0f;
    }

    const int nkb = (q0 + 64) / 32;  // causal: key blocks 0 .. nkb-1

    for (int kb = 0; kb < nkb; kb++) {
        const int k0 = kb * 32;
        // load K,V tiles: 32x64 each -> 512 float4, 2 per thread
#pragma unroll
        for (int it = 0; it < 2; it++) {
            int fi = tid + it * 256;
            int r = fi >> 4;
            int c = (fi & 15) * 4;
            *reinterpret_cast<float4*>(&Ks[r * AT_QSTR + c]) =
                *reinterpret_cast<const float4*>(Kg + (k0 + r) * HDIM + c);
            *reinterpret_cast<float4*>(&Vs[r * AT_QSTR + c]) =
                *reinterpret_cast<const float4*>(Vg + (k0 + r) * HDIM + c);
        }
        __syncthreads();

        // S = Q K^T for this tile: rows 4*ty+i, cols tx+16*j (j<2)
        float s[4][2] = {{0.0f, 0.0f}, {0.0f, 0.0f}, {0.0f, 0.0f}, {0.0f, 0.0f}};
#pragma unroll
        for (int d = 0; d < 64; d += 4) {
            float4 qv[4], kv[2];
#pragma unroll
            for (int i = 0; i < 4; i++)
                qv[i] = *reinterpret_cast<const float4*>(&Qs[(4 * ty + i) * AT_QSTR + d]);
#pragma unroll
            for (int j = 0; j < 2; j++)
                kv[j] = *reinterpret_cast<const float4*>(&Ks[(tx + 16 * j) * AT_QSTR + d]);
#pragma unroll
            for (int i = 0; i < 4; i++)
#pragma unroll
                for (int j = 0; j < 2; j++) {
                    s[i][j] = fmaf(qv[i].x, kv[j].x, s[i][j]);
                    s[i][j] = fmaf(qv[i].y, kv[j].y, s[i][j]);
                    s[i][j] = fmaf(qv[i].z, kv[j].z, s[i][j]);
                    s[i][j] = fmaf(qv[i].w, kv[j].w, s[i][j]);
                }
        }

        // causal mask (only for the last two key blocks of this q block)
        if (k0 + 31 > q0) {
#pragma unroll
            for (int i = 0; i < 4; i++) {
                int row = q0 + 4 * ty + i;
#pragma unroll
                for (int j = 0; j < 2; j++) {
                    int col = k0 + tx + 16 * j;
                    if (col > row) s[i][j] = -1e30f;
                }
            }
        }

        // online softmax
#pragma unroll
        for (int i = 0; i < 4; i++) {
            float rm = fmaxf(s[i][0], s[i][1]);
            rm = fmaxf(rm, __shfl_xor_sync(0xffffffffu, rm, 1));
            rm = fmaxf(rm, __shfl_xor_sync(0xffffffffu, rm, 2));
            rm = fmaxf(rm, __shfl_xor_sync(0xffffffffu, rm, 4));
            rm = fmaxf(rm, __shfl_xor_sync(0xffffffffu, rm, 8));
            float mn = fmaxf(m_i[i], rm);
            float corr = __expf(m_i[i] - mn);
            float p0 = __expf(s[i][0] - mn);
            float p1 = __expf(s[i][1] - mn);
            float rs = p0 + p1;
            rs += __shfl_xor_sync(0xffffffffu, rs, 1);
            rs += __shfl_xor_sync(0xffffffffu, rs, 2);
            rs += __shfl_xor_sync(0xffffffffu, rs, 4);
            rs += __shfl_xor_sync(0xffffffffu, rs, 8);
            l_i[i] = l_i[i] * corr + rs;
            m_i[i] = mn;
#pragma unroll
            for (int j = 0; j < 4; j++) o[i][j] *= corr;
            Ss[(4 * ty + i) * AT_SSTR + tx] = p0;
            Ss[(4 * ty + i) * AT_SSTR + tx + 16] = p1;
        }
        __syncthreads();

        // O += P @ V : rows 4*ty+i, dims tx+16*j
#pragma unroll
        for (int k = 0; k < 32; k += 4) {
            float p[4][4];
#pragma unroll
            for (int i = 0; i < 4; i++) {
                float4 pv = *reinterpret_cast<const float4*>(&Ss[(4 * ty + i) * AT_SSTR + k]);
                p[i][0] = pv.x; p[i][1] = pv.y; p[i][2] = pv.z; p[i][3] = pv.w;
            }
#pragma unroll
            for (int kk = 0; kk < 4; kk++) {
#pragma unroll
                for (int j = 0; j < 4; j++) {
                    float vv = Vs[(k + kk) * AT_QSTR + tx + 16 * j];
#pragma unroll
                    for (int i = 0; i < 4; i++) o[i][j] = fmaf(p[i][kk], vv, o[i][j]);
                }
            }
        }
        __syncthreads();
    }

    // write context in (B, L, H*hd) layout for the output projection
    const int b = bh >> 4;
    const int h = bh & 15;
#pragma unroll
    for (int i = 0; i < 4; i++) {
        float inv = 1.0f / l_i[i];
        int row = q0 + 4 * ty + i;
        float* dst = ctx + ((size_t)(b * SEQ + row) * DMODEL) + h * HDIM;
#pragma unroll
        for (int j = 0; j < 4; j++) dst[tx + 16 * j] = o[i][j] * inv;
    }
}

// ---------------------------------------------------------------------------
// Launch
// ---------------------------------------------------------------------------
static float* sym_addr(const void* symbol) {
    void* p = nullptr;
    cudaGetSymbolAddress(&p, symbol);
    return reinterpret_cast<float*>(p);
}

extern "C" void kernel_launch(void* const* d_in, const int* in_sizes, int n_in,
                              void* d_out, int out_size) {
    const float* x  = (const float*)d_in[0];
    const float* Wq = (const float*)d_in[1];
    const float* Wk = (const float*)d_in[2];
    const float* Wv = (const float*)d_in[3];
    const float* Wo = (const float*)d_in[4];
    float* out = (float*)d_out;

    float* q   = sym_addr(g_q);
    float* k   = sym_addr(g_k);
    float* v   = sym_addr(g_v);
    float* ctx = sym_addr(g_ctx);

    dim3 gg(DMODEL / 128, MTOT / 128);   // (8, 32)
    sgemm_nt<1><<<gg, 256>>>(x, Wq, q, MTOT, DMODEL, DMODEL);
    sgemm_nt<1><<<gg, 256>>>(x, Wk, k, MTOT, DMODEL, DMODEL);
    sgemm_nt<1><<<gg, 256>>>(x, Wv, v, MTOT, DMODEL, DMODEL);

    dim3 ga(SEQ / 64, BATCH * NHEAD);    // (32, 32)
    flash_attn<<<ga, 256>>>(q, k, v, ctx);

    sgemm_nt<0><<<gg, 256>>>(ctx, Wo, out, MTOT, DMODEL, DMODEL);
}

// round 4
// speedup vs baseline: 1.3960x; 1.3960x over previous
#include <cuda_runtime.h>
#include <cuda_bf16.h>
#include <cstdint>

// ---------------------------------------------------------------------------
// Problem constants: B=2, L=2048, D=1024, H=16, hd=64
// ---------------------------------------------------------------------------
#define BATCH 2
#define SEQ   2048
#define DMODEL 1024
#define NHEAD 16
#define HDIM  64
#define MTOT  (BATCH * SEQ)          // 4096
#define SOFTMAX_SCALE 0.125f         // 1/sqrt(64)

// Scratch (device globals; no runtime allocation allowed)
__device__ float g_q[MTOT * DMODEL];
__device__ float g_k[MTOT * DMODEL];
__device__ float g_v[MTOT * DMODEL];
__device__ float g_ctx[MTOT * DMODEL];

__device__ __forceinline__ uint32_t f2tf32(float x) {
    uint32_t r;
    asm("cvt.rna.tf32.f32 %0, %1;" : "=r"(r) : "f"(x));
    return r;
}

__device__ __forceinline__ void mma_tf32(float* d, const uint32_t* a, const uint32_t* b) {
    asm volatile(
        "mma.sync.aligned.m16n8k8.row.col.f32.tf32.tf32.f32 "
        "{%0,%1,%2,%3}, {%4,%5,%6,%7}, {%8,%9}, {%0,%1,%2,%3};\n"
        : "+f"(d[0]), "+f"(d[1]), "+f"(d[2]), "+f"(d[3])
        : "r"(a[0]), "r"(a[1]), "r"(a[2]), "r"(a[3]), "r"(b[0]), "r"(b[1]));
}

// ---------------------------------------------------------------------------
// TF32 mma.sync GEMM: C = A @ B^T.
// A:[4096,1024], B:[1024,1024] row-major. CTA tile 128x128, BK=32,
// double-buffered smem, m-major stride-36 padding (conflict-free frag LDS).
// 256 threads = 8 warps as 2(m) x 4(n); warp tile 64x32; mma m16n8k8.
// MODE 0: C row-major [M, DMODEL];  MODE 1: scatter to (B,H,L,hd).
// ---------------------------------------------------------------------------
#define GK 32                        // K per chunk
#define GSTR 36                      // padded row stride (floats)
#define GSTAGE (128 * GSTR)          // floats per operand per stage
#define GSMEM_BYTES (4 * GSTAGE * 4) // 2 stages * (A+B)  = 73728 B

template <int MODE>
__global__ __launch_bounds__(256) void gemm_mma(const float* __restrict__ A,
                                                const float* __restrict__ B,
                                                float* __restrict__ C) {
    extern __shared__ float sm[];
    float* As = sm;                  // [2][128][GSTR]
    float* Bs = sm + 2 * GSTAGE;     // [2][128][GSTR]

    const int tid = threadIdx.x;
    const int bm = blockIdx.y * 128;
    const int bn = blockIdx.x * 128;

    // global-load mapping: 2 threads per row; thread covers k = lc + 8u (+0..3)
    const int lr = tid >> 1;         // 0..127
    const int lc = (tid & 1) * 4;    // 0 or 4

    const int wid = tid >> 5;
    const int lane = tid & 31;
    const int wm = (wid & 1) * 64;   // warp row offset in CTA tile
    const int wn = (wid >> 1) * 32;  // warp col offset in CTA tile
    const int gid = lane >> 2;       // 0..7
    const int tig = lane & 3;        // 0..3

    const float* Ag = A + (size_t)(bm + lr) * DMODEL + lc;
    const float* Bg = B + (size_t)(bn + lr) * DMODEL + lc;

    float acc[4][4][4];              // [mt][nt][frag]
#pragma unroll
    for (int i = 0; i < 4; i++)
#pragma unroll
        for (int j = 0; j < 4; j++)
#pragma unroll
            for (int r = 0; r < 4; r++) acc[i][j][r] = 0.0f;

    float4 ra[4], rb[4];

    // prefetch chunk 0
#pragma unroll
    for (int u = 0; u < 4; u++) {
        ra[u] = *reinterpret_cast<const float4*>(Ag + u * 8);
        rb[u] = *reinterpret_cast<const float4*>(Bg + u * 8);
    }
    // store stage 0 (tf32-converted)
    {
        uint32_t* Asb = reinterpret_cast<uint32_t*>(As);
        uint32_t* Bsb = reinterpret_cast<uint32_t*>(Bs);
#pragma unroll
        for (int u = 0; u < 4; u++) {
            const int ko = lc + 8 * u;
            uint4 av = make_uint4(f2tf32(ra[u].x), f2tf32(ra[u].y), f2tf32(ra[u].z), f2tf32(ra[u].w));
            uint4 bv = make_uint4(f2tf32(rb[u].x), f2tf32(rb[u].y), f2tf32(rb[u].z), f2tf32(rb[u].w));
            *reinterpret_cast<uint4*>(&Asb[lr * GSTR + ko]) = av;
            *reinterpret_cast<uint4*>(&Bsb[lr * GSTR + ko]) = bv;
        }
    }
    __syncthreads();

    const int NCHUNK = DMODEL / GK;  // 32
    for (int c = 0; c < NCHUNK; c++) {
        const int s = c & 1;
        if (c + 1 < NCHUNK) {
            const int k0 = (c + 1) * GK;
#pragma unroll
            for (int u = 0; u < 4; u++) {
                ra[u] = *reinterpret_cast<const float4*>(Ag + k0 + u * 8);
                rb[u] = *reinterpret_cast<const float4*>(Bg + k0 + u * 8);
            }
        }

        const uint32_t* Asb = reinterpret_cast<const uint32_t*>(As + s * GSTAGE);
        const uint32_t* Bsb = reinterpret_cast<const uint32_t*>(Bs + s * GSTAGE);

#pragma unroll
        for (int kk = 0; kk < GK; kk += 8) {
            uint32_t af[4][4], bf[4][2];
#pragma unroll
            for (int mt = 0; mt < 4; mt++) {
                const int row = wm + mt * 16;
                af[mt][0] = Asb[(row + gid) * GSTR + kk + tig];
                af[mt][1] = Asb[(row + gid + 8) * GSTR + kk + tig];
                af[mt][2] = Asb[(row + gid) * GSTR + kk + tig + 4];
                af[mt][3] = Asb[(row + gid + 8) * GSTR + kk + tig + 4];
            }
#pragma unroll
            for (int nt = 0; nt < 4; nt++) {
                const int col = wn + nt * 8;
                bf[nt][0] = Bsb[(col + gid) * GSTR + kk + tig];
                bf[nt][1] = Bsb[(col + gid) * GSTR + kk + tig + 4];
            }
#pragma unroll
            for (int mt = 0; mt < 4; mt++)
#pragma unroll
                for (int nt = 0; nt < 4; nt++) mma_tf32(acc[mt][nt], af[mt], bf[nt]);
        }
        __syncthreads();

        if (c + 1 < NCHUNK) {
            uint32_t* Aw = reinterpret_cast<uint32_t*>(As + (s ^ 1) * GSTAGE);
            uint32_t* Bw = reinterpret_cast<uint32_t*>(Bs + (s ^ 1) * GSTAGE);
#pragma unroll
            for (int u = 0; u < 4; u++) {
                const int ko = lc + 8 * u;
                uint4 av = make_uint4(f2tf32(ra[u].x), f2tf32(ra[u].y), f2tf32(ra[u].z), f2tf32(ra[u].w));
                uint4 bv = make_uint4(f2tf32(rb[u].x), f2tf32(rb[u].y), f2tf32(rb[u].z), f2tf32(rb[u].w));
                *reinterpret_cast<uint4*>(&Aw[lr * GSTR + ko]) = av;
                *reinterpret_cast<uint4*>(&Bw[lr * GSTR + ko]) = bv;
            }
            __syncthreads();
        }
    }

    // epilogue: c0,c1 -> (row, col..col+1); c2,c3 -> (row+8, col..col+1)
#pragma unroll
    for (int mt = 0; mt < 4; mt++) {
        const int row0 = bm + wm + mt * 16 + gid;
#pragma unroll
        for (int nt = 0; nt < 4; nt++) {
            const int gcol = bn + wn + nt * 8 + 2 * tig;
#pragma unroll
            for (int half = 0; half < 2; half++) {
                const int row = row0 + 8 * half;
                float2 val = make_float2(acc[mt][nt][2 * half], acc[mt][nt][2 * half + 1]);
                if (MODE == 0) {
                    *reinterpret_cast<float2*>(C + (size_t)row * DMODEL + gcol) = val;
                } else {
                    const int b = row >> 11;
                    const int l = row & (SEQ - 1);
                    const int h = gcol >> 6;
                    const int dd = gcol & (HDIM - 1);
                    *reinterpret_cast<float2*>(
                        C + (((size_t)(b * NHEAD + h) * SEQ) + l) * HDIM + dd) = val;
                }
            }
        }
    }
}

// ---------------------------------------------------------------------------
// Flash attention (fp32, causal). Q/K/V in (B,H,L,hd) layout. Unchanged.
// ---------------------------------------------------------------------------
#define AT_QSTR 68
#define AT_SSTR 36

__global__ __launch_bounds__(256) void flash_attn(const float* __restrict__ Q,
                                                  const float* __restrict__ K,
                                                  const float* __restrict__ V,
                                                  float* __restrict__ ctx) {
    __shared__ float Qs[64 * AT_QSTR];
    __shared__ float Ks[32 * AT_QSTR];
    __shared__ float Vs[32 * AT_QSTR];
    __shared__ float Ss[64 * AT_SSTR];

    const int tid = threadIdx.x;
    const int ty = tid >> 4;
    const int tx = tid & 15;
    const int bh = blockIdx.y;
    const int q0 = blockIdx.x * 64;

    const float* Qg = Q + ((size_t)bh * SEQ + q0) * HDIM;
    const float* Kg = K + (size_t)bh * SEQ * HDIM;
    const float* Vg = V + (size_t)bh * SEQ * HDIM;

#pragma unroll
    for (int it = 0; it < 4; it++) {
        int fi = tid + it * 256;
        int r = fi >> 4;
        int c = (fi & 15) * 4;
        float4 v = *reinterpret_cast<const float4*>(Qg + r * HDIM + c);
        float4 w = make_float4(v.x * SOFTMAX_SCALE, v.y * SOFTMAX_SCALE,
                               v.z * SOFTMAX_SCALE, v.w * SOFTMAX_SCALE);
        *reinterpret_cast<float4*>(&Qs[r * AT_QSTR + c]) = w;
    }

    float m_i[4], l_i[4], o[4][4];
#pragma unroll
    for (int i = 0; i < 4; i++) {
        m_i[i] = -1e30f;
        l_i[i] = 0.0f;
#pragma unroll
        for (int j = 0; j < 4; j++) o[i][j] = 0.0f;
    }

    const int nkb = (q0 + 64) / 32;

    for (int kb = 0; kb < nkb; kb++) {
        const int k0 = kb * 32;
#pragma unroll
        for (int it = 0; it < 2; it++) {
            int fi = tid + it * 256;
            int r = fi >> 4;
            int c = (fi & 15) * 4;
            *reinterpret_cast<float4*>(&Ks[r * AT_QSTR + c]) =
                *reinterpret_cast<const float4*>(Kg + (k0 + r) * HDIM + c);
            *reinterpret_cast<float4*>(&Vs[r * AT_QSTR + c]) =
                *reinterpret_cast<const float4*>(Vg + (k0 + r) * HDIM + c);
        }
        __syncthreads();

        float s[4][2] = {{0.0f, 0.0f}, {0.0f, 0.0f}, {0.0f, 0.0f}, {0.0f, 0.0f}};
#pragma unroll
        for (int d = 0; d < 64; d += 4) {
            float4 qv[4], kv[2];
#pragma unroll
            for (int i = 0; i < 4; i++)
                qv[i] = *reinterpret_cast<const float4*>(&Qs[(4 * ty + i) * AT_QSTR + d]);
#pragma unroll
            for (int j = 0; j < 2; j++)
                kv[j] = *reinterpret_cast<const float4*>(&Ks[(tx + 16 * j) * AT_QSTR + d]);
#pragma unroll
            for (int i = 0; i < 4; i++)
#pragma unroll
                for (int j = 0; j < 2; j++) {
                    s[i][j] = fmaf(qv[i].x, kv[j].x, s[i][j]);
                    s[i][j] = fmaf(qv[i].y, kv[j].y, s[i][j]);
                    s[i][j] = fmaf(qv[i].z, kv[j].z, s[i][j]);
                    s[i][j] = fmaf(qv[i].w, kv[j].w, s[i][j]);
                }
        }

        if (k0 + 31 > q0) {
#pragma unroll
            for (int i = 0; i < 4; i++) {
                int row = q0 + 4 * ty + i;
#pragma unroll
                for (int j = 0; j < 2; j++) {
                    int col = k0 + tx + 16 * j;
                    if (col > row) s[i][j] = -1e30f;
                }
            }
        }

#pragma unroll
        for (int i = 0; i < 4; i++) {
            float rm = fmaxf(s[i][0], s[i][1]);
            rm = fmaxf(rm, __shfl_xor_sync(0xffffffffu, rm, 1));
            rm = fmaxf(rm, __shfl_xor_sync(0xffffffffu, rm, 2));
            rm = fmaxf(rm, __shfl_xor_sync(0xffffffffu, rm, 4));
            rm = fmaxf(rm, __shfl_xor_sync(0xffffffffu, rm, 8));
            float mn = fmaxf(m_i[i], rm);
            float corr = __expf(m_i[i] - mn);
            float p0 = __expf(s[i][0] - mn);
            float p1 = __expf(s[i][1] - mn);
            float rs = p0 + p1;
            rs += __shfl_xor_sync(0xffffffffu, rs, 1);
            rs += __shfl_xor_sync(0xffffffffu, rs, 2);
            rs += __shfl_xor_sync(0xffffffffu, rs, 4);
            rs += __shfl_xor_sync(0xffffffffu, rs, 8);
            l_i[i] = l_i[i] * corr + rs;
            m_i[i] = mn;
#pragma unroll
            for (int j = 0; j < 4; j++) o[i][j] *= corr;
            Ss[(4 * ty + i) * AT_SSTR + tx] = p0;
            Ss[(4 * ty + i) * AT_SSTR + tx + 16] = p1;
        }
        __syncthreads();

#pragma unroll
        for (int k = 0; k < 32; k += 4) {
            float p[4][4];
#pragma unroll
            for (int i = 0; i < 4; i++) {
                float4 pv = *reinterpret_cast<const float4*>(&Ss[(4 * ty + i) * AT_SSTR + k]);
                p[i][0] = pv.x; p[i][1] = pv.y; p[i][2] = pv.z; p[i][3] = pv.w;
            }
#pragma unroll
            for (int kk = 0; kk < 4; kk++) {
#pragma unroll
                for (int j = 0; j < 4; j++) {
                    float vv = Vs[(k + kk) * AT_QSTR + tx + 16 * j];
#pragma unroll
                    for (int i = 0; i < 4; i++) o[i][j] = fmaf(p[i][kk], vv, o[i][j]);
                }
            }
        }
        __syncthreads();
    }

    const int b = bh >> 4;
    const int h = bh & 15;
#pragma unroll
    for (int i = 0; i < 4; i++) {
        float inv = 1.0f / l_i[i];
        int row = q0 + 4 * ty + i;
        float* dst = ctx + ((size_t)(b * SEQ + row) * DMODEL) + h * HDIM;
#pragma unroll
        for (int j = 0; j < 4; j++) dst[tx + 16 * j] = o[i][j] * inv;
    }
}

// ---------------------------------------------------------------------------
// Launch
// ---------------------------------------------------------------------------
static float* sym_addr(const void* symbol) {
    void* p = nullptr;
    cudaGetSymbolAddress(&p, symbol);
    return reinterpret_cast<float*>(p);
}

extern "C" void kernel_launch(void* const* d_in, const int* in_sizes, int n_in,
                              void* d_out, int out_size) {
    const float* x  = (const float*)d_in[0];
    const float* Wq = (const float*)d_in[1];
    const float* Wk = (const float*)d_in[2];
    const float* Wv = (const float*)d_in[3];
    const float* Wo = (const float*)d_in[4];
    float* out = (float*)d_out;

    float* q   = sym_addr(g_q);
    float* k   = sym_addr(g_k);
    float* v   = sym_addr(g_v);
    float* ctx = sym_addr(g_ctx);

    cudaFuncSetAttribute(gemm_mma<1>, cudaFuncAttributeMaxDynamicSharedMemorySize, GSMEM_BYTES);
    cudaFuncSetAttribute(gemm_mma<0>, cudaFuncAttributeMaxDynamicSharedMemorySize, GSMEM_BYTES);

    dim3 gg(DMODEL / 128, MTOT / 128);   // (8, 32)
    gemm_mma<1><<<gg, 256, GSMEM_BYTES>>>(x, Wq, q);
    gemm_mma<1><<<gg, 256, GSMEM_BYTES>>>(x, Wk, k);
    gemm_mma<1><<<gg, 256, GSMEM_BYTES>>>(x, Wv, v);

    dim3 ga(SEQ / 64, BATCH * NHEAD);    // (32, 32)
    flash_attn<<<ga, 256>>>(q, k, v, ctx);

    gemm_mma<0><<<gg, 256, GSMEM_BYTES>>>(ctx, Wo, out);
}

// round 5
// speedup vs baseline: 2.5192x; 1.8046x over previous
#include <cuda_runtime.h>
#include <cuda_bf16.h>
#include <cstdint>

// ---------------------------------------------------------------------------
// Problem constants: B=2, L=2048, D=1024, H=16, hd=64
// ---------------------------------------------------------------------------
#define BATCH 2
#define SEQ   2048
#define DMODEL 1024
#define NHEAD 16
#define HDIM  64
#define MTOT  (BATCH * SEQ)          // 4096

// Scratch (device globals; no runtime allocation allowed)
__device__ float g_q[MTOT * DMODEL];
__device__ float g_k[MTOT * DMODEL];
__device__ float g_v[MTOT * DMODEL];
__device__ float g_ctx[MTOT * DMODEL];

__device__ __forceinline__ uint32_t f2tf32(float x) {
    uint32_t r;
    asm("cvt.rna.tf32.f32 %0, %1;" : "=r"(r) : "f"(x));
    return r;
}
__device__ __forceinline__ float ex2(float x) {
    float r;
    asm("ex2.approx.f32 %0, %1;" : "=f"(r) : "f"(x));
    return r;
}
__device__ __forceinline__ uint32_t smem_u32(const void* p) {
    uint32_t a;
    asm("{ .reg .u64 t; cvta.to.shared.u64 t, %1; cvt.u32.u64 %0, t; }" : "=r"(a) : "l"(p));
    return a;
}
__device__ __forceinline__ void cp16(uint32_t smem, const float* g) {
    asm volatile("cp.async.cg.shared.global [%0], [%1], 16;"
                 :: "r"(smem), "l"(__cvta_generic_to_global(g)));
}

__device__ __forceinline__ void mma_tf32(float* d, const uint32_t* a, const uint32_t* b) {
    asm volatile(
        "mma.sync.aligned.m16n8k8.row.col.f32.tf32.tf32.f32 "
        "{%0,%1,%2,%3}, {%4,%5,%6,%7}, {%8,%9}, {%0,%1,%2,%3};\n"
        : "+f"(d[0]), "+f"(d[1]), "+f"(d[2]), "+f"(d[3])
        : "r"(a[0]), "r"(a[1]), "r"(a[2]), "r"(a[3]), "r"(b[0]), "r"(b[1]));
}

// ---------------------------------------------------------------------------
// TF32 mma.sync GEMM: C = A @ B^T.  (validated in R4)
// MODE 0: C row-major;  MODE 1: scatter to (B,H,L,hd) with tf32 pre-rounding.
// ---------------------------------------------------------------------------
#define GK 32
#define GSTR 36
#define GSTAGE (128 * GSTR)
#define GSMEM_BYTES (4 * GSTAGE * 4)

template <int MODE>
__global__ __launch_bounds__(256) void gemm_mma(const float* __restrict__ A,
                                                const float* __restrict__ B,
                                                float* __restrict__ C) {
    extern __shared__ float sm[];
    float* As = sm;
    float* Bs = sm + 2 * GSTAGE;

    const int tid = threadIdx.x;
    const int bm = blockIdx.y * 128;
    const int bn = blockIdx.x * 128;

    const int lr = tid >> 1;
    const int lc = (tid & 1) * 4;

    const int wid = tid >> 5;
    const int lane = tid & 31;
    const int wm = (wid & 1) * 64;
    const int wn = (wid >> 1) * 32;
    const int gid = lane >> 2;
    const int tig = lane & 3;

    const float* Ag = A + (size_t)(bm + lr) * DMODEL + lc;
    const float* Bg = B + (size_t)(bn + lr) * DMODEL + lc;

    float acc[4][4][4];
#pragma unroll
    for (int i = 0; i < 4; i++)
#pragma unroll
        for (int j = 0; j < 4; j++)
#pragma unroll
            for (int r = 0; r < 4; r++) acc[i][j][r] = 0.0f;

    float4 ra[4], rb[4];

#pragma unroll
    for (int u = 0; u < 4; u++) {
        ra[u] = *reinterpret_cast<const float4*>(Ag + u * 8);
        rb[u] = *reinterpret_cast<const float4*>(Bg + u * 8);
    }
    {
        uint32_t* Asb = reinterpret_cast<uint32_t*>(As);
        uint32_t* Bsb = reinterpret_cast<uint32_t*>(Bs);
#pragma unroll
        for (int u = 0; u < 4; u++) {
            const int ko = lc + 8 * u;
            uint4 av = make_uint4(f2tf32(ra[u].x), f2tf32(ra[u].y), f2tf32(ra[u].z), f2tf32(ra[u].w));
            uint4 bv = make_uint4(f2tf32(rb[u].x), f2tf32(rb[u].y), f2tf32(rb[u].z), f2tf32(rb[u].w));
            *reinterpret_cast<uint4*>(&Asb[lr * GSTR + ko]) = av;
            *reinterpret_cast<uint4*>(&Bsb[lr * GSTR + ko]) = bv;
        }
    }
    __syncthreads();

    const int NCHUNK = DMODEL / GK;
    for (int c = 0; c < NCHUNK; c++) {
        const int s = c & 1;
        if (c + 1 < NCHUNK) {
            const int k0 = (c + 1) * GK;
#pragma unroll
            for (int u = 0; u < 4; u++) {
                ra[u] = *reinterpret_cast<const float4*>(Ag + k0 + u * 8);
                rb[u] = *reinterpret_cast<const float4*>(Bg + k0 + u * 8);
            }
        }

        const uint32_t* Asb = reinterpret_cast<const uint32_t*>(As + s * GSTAGE);
        const uint32_t* Bsb = reinterpret_cast<const uint32_t*>(Bs + s * GSTAGE);

#pragma unroll
        for (int kk = 0; kk < GK; kk += 8) {
            uint32_t af[4][4], bf[4][2];
#pragma unroll
            for (int mt = 0; mt < 4; mt++) {
                const int row = wm + mt * 16;
                af[mt][0] = Asb[(row + gid) * GSTR + kk + tig];
                af[mt][1] = Asb[(row + gid + 8) * GSTR + kk + tig];
                af[mt][2] = Asb[(row + gid) * GSTR + kk + tig + 4];
                af[mt][3] = Asb[(row + gid + 8) * GSTR + kk + tig + 4];
            }
#pragma unroll
            for (int nt = 0; nt < 4; nt++) {
                const int col = wn + nt * 8;
                bf[nt][0] = Bsb[(col + gid) * GSTR + kk + tig];
                bf[nt][1] = Bsb[(col + gid) * GSTR + kk + tig + 4];
            }
#pragma unroll
            for (int mt = 0; mt < 4; mt++)
#pragma unroll
                for (int nt = 0; nt < 4; nt++) mma_tf32(acc[mt][nt], af[mt], bf[nt]);
        }
        __syncthreads();

        if (c + 1 < NCHUNK) {
            uint32_t* Aw = reinterpret_cast<uint32_t*>(As + (s ^ 1) * GSTAGE);
            uint32_t* Bw = reinterpret_cast<uint32_t*>(Bs + (s ^ 1) * GSTAGE);
#pragma unroll
            for (int u = 0; u < 4; u++) {
                const int ko = lc + 8 * u;
                uint4 av = make_uint4(f2tf32(ra[u].x), f2tf32(ra[u].y), f2tf32(ra[u].z), f2tf32(ra[u].w));
                uint4 bv = make_uint4(f2tf32(rb[u].x), f2tf32(rb[u].y), f2tf32(rb[u].z), f2tf32(rb[u].w));
                *reinterpret_cast<uint4*>(&Aw[lr * GSTR + ko]) = av;
                *reinterpret_cast<uint4*>(&Bw[lr * GSTR + ko]) = bv;
            }
            __syncthreads();
        }
    }

#pragma unroll
    for (int mt = 0; mt < 4; mt++) {
        const int row0 = bm + wm + mt * 16 + gid;
#pragma unroll
        for (int nt = 0; nt < 4; nt++) {
            const int gcol = bn + wn + nt * 8 + 2 * tig;
#pragma unroll
            for (int half = 0; half < 2; half++) {
                const int row = row0 + 8 * half;
                float v0 = acc[mt][nt][2 * half];
                float v1 = acc[mt][nt][2 * half + 1];
                if (MODE == 0) {
                    *reinterpret_cast<float2*>(C + (size_t)row * DMODEL + gcol) =
                        make_float2(v0, v1);
                } else {
                    // tf32 pre-round Q/K/V so the attention kernel feeds smem
                    // bits directly into mma with zero conversions.
                    const int b = row >> 11;
                    const int l = row & (SEQ - 1);
                    const int h = gcol >> 6;
                    const int dd = gcol & (HDIM - 1);
                    *reinterpret_cast<float2*>(
                        C + (((size_t)(b * NHEAD + h) * SEQ) + l) * HDIM + dd) =
                        make_float2(__uint_as_float(f2tf32(v0)),
                                    __uint_as_float(f2tf32(v1)));
                }
            }
        }
    }
}

// ---------------------------------------------------------------------------
// Flash attention, tf32 mma.sync, causal.
// BQ=128 (8 warps x m16), BK=64, hd=64. cp.async double-buffered K/V.
// Q/K/V arrive tf32-pre-rounded in (B,H,L,64).
// ---------------------------------------------------------------------------
#define FA_BQ 128
#define FA_BK 64
#define FA_QSTR 68
#define FA_KSTR 68
#define FA_VSTR 72
#define FA_SMEM_BYTES ((128 * FA_QSTR + 2 * 64 * FA_KSTR + 2 * 64 * FA_VSTR) * 4)

__device__ __forceinline__ void fa_load_kv(uint32_t ks_a, uint32_t vs_a,
                                           const float* Kg, const float* Vg,
                                           int k0, int stage, int tid) {
    const uint32_t ko = ks_a + (uint32_t)stage * (64 * FA_KSTR * 4);
    const uint32_t vo = vs_a + (uint32_t)stage * (64 * FA_VSTR * 4);
#pragma unroll
    for (int u = 0; u < 4; u++) {
        const int idx = u * 256 + tid;
        const int r = idx >> 4;
        const int ch = idx & 15;
        cp16(ko + (uint32_t)(r * FA_KSTR + ch * 4) * 4, Kg + (size_t)(k0 + r) * HDIM + ch * 4);
        cp16(vo + (uint32_t)(r * FA_VSTR + ch * 4) * 4, Vg + (size_t)(k0 + r) * HDIM + ch * 4);
    }
}

__global__ __launch_bounds__(256, 2) void flash_mma(const float* __restrict__ Q,
                                                    const float* __restrict__ K,
                                                    const float* __restrict__ V,
                                                    float* __restrict__ ctx) {
    extern __shared__ float fs[];
    float* Qs = fs;
    float* Ks = fs + 128 * FA_QSTR;
    float* Vs = fs + 128 * FA_QSTR + 2 * 64 * FA_KSTR;

    const int tid = threadIdx.x;
    const int w = tid >> 5;
    const int lane = tid & 31;
    const int gid = lane >> 2;
    const int tig = lane & 3;
    const int bh = blockIdx.y;
    const int qb = (int)gridDim.x - 1 - (int)blockIdx.x;   // heavy blocks first
    const int q0 = qb * FA_BQ;

    const float* Qg = Q + ((size_t)bh * SEQ + q0) * HDIM;
    const float* Kg = K + (size_t)bh * SEQ * HDIM;
    const float* Vg = V + (size_t)bh * SEQ * HDIM;

    const uint32_t qs_a = smem_u32(Qs);
    const uint32_t ks_a = smem_u32(Ks);
    const uint32_t vs_a = smem_u32(Vs);

    // Q tile: 128 rows x 16 16B-chunks
#pragma unroll
    for (int u = 0; u < 8; u++) {
        const int idx = u * 256 + tid;
        const int r = idx >> 4;
        const int ch = idx & 15;
        cp16(qs_a + (uint32_t)(r * FA_QSTR + ch * 4) * 4, Qg + (size_t)r * HDIM + ch * 4);
    }
    fa_load_kv(ks_a, vs_a, Kg, Vg, 0, 0, tid);
    asm volatile("cp.async.commit_group;");

    float o[8][4];
#pragma unroll
    for (int nt = 0; nt < 8; nt++)
#pragma unroll
        for (int e = 0; e < 4; e++) o[nt][e] = 0.0f;
    float m0 = -1e30f, m1 = -1e30f, l0 = 0.0f, l1 = 0.0f;

    const float CEXP = 0.125f * 1.44269504089f;    // softmax scale * log2(e)
    const int nkb = 2 * qb + 2;
    const int rq = 16 * w + gid;                    // warp-local Q row (gid half)

    for (int kb = 0; kb < nkb; kb++) {
        if (kb + 1 < nkb) {
            fa_load_kv(ks_a, vs_a, Kg, Vg, (kb + 1) * FA_BK, (kb + 1) & 1, tid);
            asm volatile("cp.async.commit_group;");
            asm volatile("cp.async.wait_group 1;");
        } else {
            asm volatile("cp.async.wait_group 0;");
        }
        __syncthreads();

        const uint32_t* Qsb = reinterpret_cast<const uint32_t*>(Qs);
        const uint32_t* Ksb = reinterpret_cast<const uint32_t*>(Ks + (kb & 1) * 64 * FA_KSTR);
        const uint32_t* Vsb = reinterpret_cast<const uint32_t*>(Vs + (kb & 1) * 64 * FA_VSTR);

        // --- S = Q K^T (16 x 64 per warp) ---
        float c[8][4];
#pragma unroll
        for (int nt = 0; nt < 8; nt++)
#pragma unroll
            for (int e = 0; e < 4; e++) c[nt][e] = 0.0f;

#pragma unroll
        for (int kk = 0; kk < 8; kk++) {
            uint32_t qa[4];
            qa[0] = Qsb[(rq) * FA_QSTR + 8 * kk + tig];
            qa[1] = Qsb[(rq + 8) * FA_QSTR + 8 * kk + tig];
            qa[2] = Qsb[(rq) * FA_QSTR + 8 * kk + tig + 4];
            qa[3] = Qsb[(rq + 8) * FA_QSTR + 8 * kk + tig + 4];
#pragma unroll
            for (int nt = 0; nt < 8; nt++) {
                uint32_t kf[2];
                kf[0] = Ksb[(8 * nt + gid) * FA_KSTR + 8 * kk + tig];
                kf[1] = Ksb[(8 * nt + gid) * FA_KSTR + 8 * kk + tig + 4];
                mma_tf32(c[nt], qa, kf);
            }
        }

        // --- scale to log2 domain + causal mask ---
        const int k0 = kb * FA_BK;
#pragma unroll
        for (int nt = 0; nt < 8; nt++)
#pragma unroll
            for (int e = 0; e < 4; e++) c[nt][e] *= CEXP;

        if (k0 + 63 > q0 + 16 * w) {
            const int r0g = q0 + rq;
#pragma unroll
            for (int nt = 0; nt < 8; nt++) {
                const int cb = k0 + 8 * nt + 2 * tig;
                if (cb > r0g) c[nt][0] = -1e30f;
                if (cb + 1 > r0g) c[nt][1] = -1e30f;
                if (cb > r0g + 8) c[nt][2] = -1e30f;
                if (cb + 1 > r0g + 8) c[nt][3] = -1e30f;
            }
        }

        // --- online softmax (two row-halves per thread) ---
        float mx0 = -1e30f, mx1 = -1e30f;
#pragma unroll
        for (int nt = 0; nt < 8; nt++) {
            mx0 = fmaxf(mx0, fmaxf(c[nt][0], c[nt][1]));
            mx1 = fmaxf(mx1, fmaxf(c[nt][2], c[nt][3]));
        }
        mx0 = fmaxf(mx0, __shfl_xor_sync(0xffffffffu, mx0, 1));
        mx0 = fmaxf(mx0, __shfl_xor_sync(0xffffffffu, mx0, 2));
        mx1 = fmaxf(mx1, __shfl_xor_sync(0xffffffffu, mx1, 1));
        mx1 = fmaxf(mx1, __shfl_xor_sync(0xffffffffu, mx1, 2));

        // floor keeps fully-masked tiles at p == 0 (mn stays >> -1e30)
        const float mn0 = fmaxf(fmaxf(m0, mx0), -1000.0f);
        const float mn1 = fmaxf(fmaxf(m1, mx1), -1000.0f);
        const float corr0 = ex2(m0 - mn0);
        const float corr1 = ex2(m1 - mn1);

        float rs0 = 0.0f, rs1 = 0.0f;
#pragma unroll
        for (int nt = 0; nt < 8; nt++) {
            c[nt][0] = ex2(c[nt][0] - mn0);
            c[nt][1] = ex2(c[nt][1] - mn0);
            c[nt][2] = ex2(c[nt][2] - mn1);
            c[nt][3] = ex2(c[nt][3] - mn1);
            rs0 += c[nt][0] + c[nt][1];
            rs1 += c[nt][2] + c[nt][3];
        }
        rs0 += __shfl_xor_sync(0xffffffffu, rs0, 1);
        rs0 += __shfl_xor_sync(0xffffffffu, rs0, 2);
        rs1 += __shfl_xor_sync(0xffffffffu, rs1, 1);
        rs1 += __shfl_xor_sync(0xffffffffu, rs1, 2);

        l0 = l0 * corr0 + rs0;
        l1 = l1 * corr1 + rs1;
        m0 = mn0;
        m1 = mn1;

#pragma unroll
        for (int nt = 0; nt < 8; nt++) {
            o[nt][0] *= corr0;
            o[nt][1] *= corr0;
            o[nt][2] *= corr1;
            o[nt][3] *= corr1;
        }

        // --- O += P V : reshape S-acc frags -> A frags via quad shuffles ---
        const int srcA = (lane & 28) | (tig >> 1);
        const int srcB = srcA + 2;
        const bool odd = (tig & 1) != 0;
#pragma unroll
        for (int j = 0; j < 8; j++) {
            const float v00 = __shfl_sync(0xffffffffu, c[j][0], srcA);
            const float v01 = __shfl_sync(0xffffffffu, c[j][1], srcA);
            const float v10 = __shfl_sync(0xffffffffu, c[j][0], srcB);
            const float v11 = __shfl_sync(0xffffffffu, c[j][1], srcB);
            const float v20 = __shfl_sync(0xffffffffu, c[j][2], srcA);
            const float v21 = __shfl_sync(0xffffffffu, c[j][3], srcA);
            const float v30 = __shfl_sync(0xffffffffu, c[j][2], srcB);
            const float v31 = __shfl_sync(0xffffffffu, c[j][3], srcB);
            uint32_t pa[4];
            pa[0] = f2tf32(odd ? v01 : v00);   // P[gid][8j+tig]
            pa[2] = f2tf32(odd ? v11 : v10);   // P[gid][8j+tig+4]
            pa[1] = f2tf32(odd ? v21 : v20);   // P[gid+8][8j+tig]
            pa[3] = f2tf32(odd ? v31 : v30);   // P[gid+8][8j+tig+4]
#pragma unroll
            for (int nt = 0; nt < 8; nt++) {
                uint32_t vf[2];
                vf[0] = Vsb[(8 * j + tig) * FA_VSTR + 8 * nt + gid];
                vf[1] = Vsb[(8 * j + tig + 4) * FA_VSTR + 8 * nt + gid];
                mma_tf32(o[nt], pa, vf);
            }
        }
        __syncthreads();
    }

    // --- normalize + write ctx in (B, L, D) layout ---
    const float inv0 = 1.0f / l0;
    const float inv1 = 1.0f / l1;
    const int b = bh >> 4;
    const int h = bh & 15;
    const int r0 = q0 + rq;
#pragma unroll
    for (int nt = 0; nt < 8; nt++) {
        const int col = h * HDIM + 8 * nt + 2 * tig;
        *reinterpret_cast<float2*>(ctx + ((size_t)(b * SEQ + r0) * DMODEL) + col) =
            make_float2(o[nt][0] * inv0, o[nt][1] * inv0);
        *reinterpret_cast<float2*>(ctx + ((size_t)(b * SEQ + r0 + 8) * DMODEL) + col) =
            make_float2(o[nt][2] * inv1, o[nt][3] * inv1);
    }
}

// ---------------------------------------------------------------------------
// Launch
// ---------------------------------------------------------------------------
static float* sym_addr(const void* symbol) {
    void* p = nullptr;
    cudaGetSymbolAddress(&p, symbol);
    return reinterpret_cast<float*>(p);
}

extern "C" void kernel_launch(void* const* d_in, const int* in_sizes, int n_in,
                              void* d_out, int out_size) {
    const float* x  = (const float*)d_in[0];
    const float* Wq = (const float*)d_in[1];
    const float* Wk = (const float*)d_in[2];
    const float* Wv = (const float*)d_in[3];
    const float* Wo = (const float*)d_in[4];
    float* out = (float*)d_out;

    float* q   = sym_addr(g_q);
    float* k   = sym_addr(g_k);
    float* v   = sym_addr(g_v);
    float* ctx = sym_addr(g_ctx);

    cudaFuncSetAttribute(gemm_mma<1>, cudaFuncAttributeMaxDynamicSharedMemorySize, GSMEM_BYTES);
    cudaFuncSetAttribute(gemm_mma<0>, cudaFuncAttributeMaxDynamicSharedMemorySize, GSMEM_BYTES);
    cudaFuncSetAttribute(flash_mma, cudaFuncAttributeMaxDynamicSharedMemorySize, FA_SMEM_BYTES);

    dim3 gg(DMODEL / 128, MTOT / 128);   // (8, 32)
    gemm_mma<1><<<gg, 256, GSMEM_BYTES>>>(x, Wq, q);
    gemm_mma<1><<<gg, 256, GSMEM_BYTES>>>(x, Wk, k);
    gemm_mma<1><<<gg, 256, GSMEM_BYTES>>>(x, Wv, v);

    dim3 ga(SEQ / FA_BQ, BATCH * NHEAD); // (16, 32)
    flash_mma<<<ga, 256, FA_SMEM_BYTES>>>(q, k, v, ctx);

    gemm_mma<0><<<gg, 256, GSMEM_BYTES>>>(ctx, Wo, out);
}

// round 6
// speedup vs baseline: 3.2391x; 1.2858x over previous
#include <cuda_runtime.h>
#include <cuda_bf16.h>
#include <cstdint>

// ---------------------------------------------------------------------------
// Problem constants: B=2, L=2048, D=1024, H=16, hd=64
// ---------------------------------------------------------------------------
#define BATCH 2
#define SEQ   2048
#define DMODEL 1024
#define NHEAD 16
#define HDIM  64
#define MTOT  (BATCH * SEQ)          // 4096

// Scratch (device globals; no runtime allocation allowed)
__device__ float g_q[MTOT * DMODEL];
__device__ float g_k[MTOT * DMODEL];
__device__ float g_v[MTOT * DMODEL];
__device__ float g_ctx[MTOT * DMODEL];
__device__ float g_xr[MTOT * DMODEL];        // tf32-rounded x
__device__ float g_wq[DMODEL * DMODEL];      // tf32-rounded weights
__device__ float g_wk[DMODEL * DMODEL];
__device__ float g_wv[DMODEL * DMODEL];
__device__ float g_wo[DMODEL * DMODEL];

__device__ __forceinline__ uint32_t f2tf32(float x) {
    uint32_t r;
    asm("cvt.rna.tf32.f32 %0, %1;" : "=r"(r) : "f"(x));
    return r;
}
__device__ __forceinline__ float ex2(float x) {
    float r;
    asm("ex2.approx.f32 %0, %1;" : "=f"(r) : "f"(x));
    return r;
}
__device__ __forceinline__ uint32_t smem_u32(const void* p) {
    uint32_t a;
    asm("{ .reg .u64 t; cvta.to.shared.u64 t, %1; cvt.u32.u64 %0, t; }" : "=r"(a) : "l"(p));
    return a;
}
__device__ __forceinline__ void cp16(uint32_t smem, const float* g) {
    asm volatile("cp.async.cg.shared.global [%0], [%1], 16;"
                 :: "r"(smem), "l"(__cvta_generic_to_global(g)));
}

__device__ __forceinline__ void mma_tf32(float* d, const uint32_t* a, const uint32_t* b) {
    asm volatile(
        "mma.sync.aligned.m16n8k8.row.col.f32.tf32.tf32.f32 "
        "{%0,%1,%2,%3}, {%4,%5,%6,%7}, {%8,%9}, {%0,%1,%2,%3};\n"
        : "+f"(d[0]), "+f"(d[1]), "+f"(d[2]), "+f"(d[3])
        : "r"(a[0]), "r"(a[1]), "r"(a[2]), "r"(a[3]), "r"(b[0]), "r"(b[1]));
}

// ---------------------------------------------------------------------------
// Elementwise tf32 (rna) pre-round: out[i] = round_tf32(in[i])
// ---------------------------------------------------------------------------
__global__ __launch_bounds__(256) void round_tf32(const float* __restrict__ in,
                                                  float* __restrict__ out, int n4) {
    const int stride = gridDim.x * blockDim.x;
    for (int i = blockIdx.x * blockDim.x + threadIdx.x; i < n4; i += stride) {
        float4 v = reinterpret_cast<const float4*>(in)[i];
        uint4 r = make_uint4(f2tf32(v.x), f2tf32(v.y), f2tf32(v.z), f2tf32(v.w));
        reinterpret_cast<uint4*>(out)[i] = r;
    }
}

// ---------------------------------------------------------------------------
// TF32 mma.sync GEMM over PRE-ROUNDED inputs, 3-stage cp.async pipeline.
// C = A @ B^T.  CTA tile 128x128, BK=32, stride-36 padded smem.
// 256 threads = 8 warps (2m x 4n); warp tile 64x32; mma m16n8k8.
// MODE 1 (QKV fused): grid.x covers N=3072; selects Wq/Wk/Wv and q/k/v by
//   column block; scatters to (B,H,L,hd) with tf32 rounding of outputs.
// MODE 0 (Wo): plain row-major C, no output rounding.
// ---------------------------------------------------------------------------
#define GK 32
#define GSTR 36
#define GSTAGE (128 * GSTR)                 // floats per operand per stage
#define GNSTAGE 3
#define GSMEM_BYTES (2 * GNSTAGE * GSTAGE * 4)   // 110592 B

template <int MODE>
__global__ __launch_bounds__(256) void gemm_mma(const float* __restrict__ A,
                                                const float* __restrict__ B0,
                                                const float* __restrict__ B1,
                                                const float* __restrict__ B2,
                                                float* __restrict__ C0,
                                                float* __restrict__ C1,
                                                float* __restrict__ C2) {
    extern __shared__ float sm[];
    const uint32_t as_a = smem_u32(sm);
    const uint32_t bs_a = as_a + GNSTAGE * GSTAGE * 4;

    const int tid = threadIdx.x;
    const int bm = blockIdx.y * 128;
    const int bnab = blockIdx.x * 128;      // absolute col (0..3071 in MODE 1)

    const float* B = B0;
    float* C = C0;
    int bn = bnab;
    if (MODE == 1) {
        if (bnab >= 2048)      { B = B2; C = C2; }
        else if (bnab >= 1024) { B = B1; C = C1; }
        bn = bnab & 1023;
    }

    const int wid = tid >> 5;
    const int lane = tid & 31;
    const int wm = (wid & 1) * 64;
    const int wn = (wid >> 1) * 32;
    const int gid = lane >> 2;
    const int tig = lane & 3;

    // cp.async mapping: 4 chunks per operand per thread (1024 chunks / 256 thr)
    // idx = u*256+tid; r = idx>>3 (row 0..127), ch = idx&7 (16B chunk in 128B row)
    const int r0c = tid >> 3;
    const int ch0 = tid & 7;

    auto issue_chunk = [&](int c, int buf) {
        const uint32_t ab = as_a + (uint32_t)buf * GSTAGE * 4;
        const uint32_t bb = bs_a + (uint32_t)buf * GSTAGE * 4;
        const int k0 = c * GK;
#pragma unroll
        for (int u = 0; u < 4; u++) {
            const int r = r0c + u * 32;
            const uint32_t so = (uint32_t)(r * GSTR + ch0 * 4) * 4;
            cp16(ab + so, A + (size_t)(bm + r) * DMODEL + k0 + ch0 * 4);
            cp16(bb + so, B + (size_t)(bn + r) * DMODEL + k0 + ch0 * 4);
        }
    };

    float acc[4][4][4];
#pragma unroll
    for (int i = 0; i < 4; i++)
#pragma unroll
        for (int j = 0; j < 4; j++)
#pragma unroll
            for (int r = 0; r < 4; r++) acc[i][j][r] = 0.0f;

    const int NCHUNK = DMODEL / GK;         // 32
#pragma unroll
    for (int s = 0; s < GNSTAGE; s++) {
        issue_chunk(s, s);
        asm volatile("cp.async.commit_group;");
    }

    for (int c = 0; c < NCHUNK; c++) {
        asm volatile("cp.async.wait_group %0;" :: "n"(GNSTAGE - 1));
        __syncthreads();

        const int buf = c % GNSTAGE;
        const uint32_t* Asb = reinterpret_cast<const uint32_t*>(sm + buf * GSTAGE);
        const uint32_t* Bsb = reinterpret_cast<const uint32_t*>(sm + (GNSTAGE + buf) * GSTAGE);

#pragma unroll
        for (int kk = 0; kk < GK; kk += 8) {
            uint32_t af[4][4], bf[4][2];
#pragma unroll
            for (int mt = 0; mt < 4; mt++) {
                const int row = wm + mt * 16;
                af[mt][0] = Asb[(row + gid) * GSTR + kk + tig];
                af[mt][1] = Asb[(row + gid + 8) * GSTR + kk + tig];
                af[mt][2] = Asb[(row + gid) * GSTR + kk + tig + 4];
                af[mt][3] = Asb[(row + gid + 8) * GSTR + kk + tig + 4];
            }
#pragma unroll
            for (int nt = 0; nt < 4; nt++) {
                const int col = wn + nt * 8;
                bf[nt][0] = Bsb[(col + gid) * GSTR + kk + tig];
                bf[nt][1] = Bsb[(col + gid) * GSTR + kk + tig + 4];
            }
#pragma unroll
            for (int mt = 0; mt < 4; mt++)
#pragma unroll
                for (int nt = 0; nt < 4; nt++) mma_tf32(acc[mt][nt], af[mt], bf[nt]);
        }
        __syncthreads();

        if (c + GNSTAGE < NCHUNK) issue_chunk(c + GNSTAGE, buf);
        asm volatile("cp.async.commit_group;");   // (possibly empty) keeps accounting
    }

#pragma unroll
    for (int mt = 0; mt < 4; mt++) {
        const int row0 = bm + wm + mt * 16 + gid;
#pragma unroll
        for (int nt = 0; nt < 4; nt++) {
            const int gcol = bn + wn + nt * 8 + 2 * tig;
#pragma unroll
            for (int half = 0; half < 2; half++) {
                const int row = row0 + 8 * half;
                float v0 = acc[mt][nt][2 * half];
                float v1 = acc[mt][nt][2 * half + 1];
                if (MODE == 0) {
                    *reinterpret_cast<float2*>(C + (size_t)row * DMODEL + gcol) =
                        make_float2(v0, v1);
                } else {
                    const int b = row >> 11;
                    const int l = row & (SEQ - 1);
                    const int h = gcol >> 6;
                    const int dd = gcol & (HDIM - 1);
                    *reinterpret_cast<float2*>(
                        C + (((size_t)(b * NHEAD + h) * SEQ) + l) * HDIM + dd) =
                        make_float2(__uint_as_float(f2tf32(v0)),
                                    __uint_as_float(f2tf32(v1)));
                }
            }
        }
    }
}

// ---------------------------------------------------------------------------
// Flash attention, tf32 mma.sync, causal.  (validated R5; ctx now tf32-rounded)
// BQ=128 (8 warps x m16), BK=64, hd=64. cp.async double-buffered K/V.
// ---------------------------------------------------------------------------
#define FA_BQ 128
#define FA_BK 64
#define FA_QSTR 68
#define FA_KSTR 68
#define FA_VSTR 72
#define FA_SMEM_BYTES ((128 * FA_QSTR + 2 * 64 * FA_KSTR + 2 * 64 * FA_VSTR) * 4)

__device__ __forceinline__ void fa_load_kv(uint32_t ks_a, uint32_t vs_a,
                                           const float* Kg, const float* Vg,
                                           int k0, int stage, int tid) {
    const uint32_t ko = ks_a + (uint32_t)stage * (64 * FA_KSTR * 4);
    const uint32_t vo = vs_a + (uint32_t)stage * (64 * FA_VSTR * 4);
#pragma unroll
    for (int u = 0; u < 4; u++) {
        const int idx = u * 256 + tid;
        const int r = idx >> 4;
        const int ch = idx & 15;
        cp16(ko + (uint32_t)(r * FA_KSTR + ch * 4) * 4, Kg + (size_t)(k0 + r) * HDIM + ch * 4);
        cp16(vo + (uint32_t)(r * FA_VSTR + ch * 4) * 4, Vg + (size_t)(k0 + r) * HDIM + ch * 4);
    }
}

__global__ __launch_bounds__(256, 2) void flash_mma(const float* __restrict__ Q,
                                                    const float* __restrict__ K,
                                                    const float* __restrict__ V,
                                                    float* __restrict__ ctx) {
    extern __shared__ float fs[];
    float* Qs = fs;
    float* Ks = fs + 128 * FA_QSTR;
    float* Vs = fs + 128 * FA_QSTR + 2 * 64 * FA_KSTR;

    const int tid = threadIdx.x;
    const int w = tid >> 5;
    const int lane = tid & 31;
    const int gid = lane >> 2;
    const int tig = lane & 3;
    const int bh = blockIdx.y;
    const int qb = (int)gridDim.x - 1 - (int)blockIdx.x;
    const int q0 = qb * FA_BQ;

    const float* Qg = Q + ((size_t)bh * SEQ + q0) * HDIM;
    const float* Kg = K + (size_t)bh * SEQ * HDIM;
    const float* Vg = V + (size_t)bh * SEQ * HDIM;

    const uint32_t qs_a = smem_u32(Qs);
    const uint32_t ks_a = smem_u32(Ks);
    const uint32_t vs_a = smem_u32(Vs);

#pragma unroll
    for (int u = 0; u < 8; u++) {
        const int idx = u * 256 + tid;
        const int r = idx >> 4;
        const int ch = idx & 15;
        cp16(qs_a + (uint32_t)(r * FA_QSTR + ch * 4) * 4, Qg + (size_t)r * HDIM + ch * 4);
    }
    fa_load_kv(ks_a, vs_a, Kg, Vg, 0, 0, tid);
    asm volatile("cp.async.commit_group;");

    float o[8][4];
#pragma unroll
    for (int nt = 0; nt < 8; nt++)
#pragma unroll
        for (int e = 0; e < 4; e++) o[nt][e] = 0.0f;
    float m0 = -1e30f, m1 = -1e30f, l0 = 0.0f, l1 = 0.0f;

    const float CEXP = 0.125f * 1.44269504089f;
    const int nkb = 2 * qb + 2;
    const int rq = 16 * w + gid;

    for (int kb = 0; kb < nkb; kb++) {
        if (kb + 1 < nkb) {
            fa_load_kv(ks_a, vs_a, Kg, Vg, (kb + 1) * FA_BK, (kb + 1) & 1, tid);
            asm volatile("cp.async.commit_group;");
            asm volatile("cp.async.wait_group 1;");
        } else {
            asm volatile("cp.async.wait_group 0;");
        }
        __syncthreads();

        const uint32_t* Qsb = reinterpret_cast<const uint32_t*>(Qs);
        const uint32_t* Ksb = reinterpret_cast<const uint32_t*>(Ks + (kb & 1) * 64 * FA_KSTR);
        const uint32_t* Vsb = reinterpret_cast<const uint32_t*>(Vs + (kb & 1) * 64 * FA_VSTR);

        float c[8][4];
#pragma unroll
        for (int nt = 0; nt < 8; nt++)
#pragma unroll
            for (int e = 0; e < 4; e++) c[nt][e] = 0.0f;

#pragma unroll
        for (int kk = 0; kk < 8; kk++) {
            uint32_t qa[4];
            qa[0] = Qsb[(rq) * FA_QSTR + 8 * kk + tig];
            qa[1] = Qsb[(rq + 8) * FA_QSTR + 8 * kk + tig];
            qa[2] = Qsb[(rq) * FA_QSTR + 8 * kk + tig + 4];
            qa[3] = Qsb[(rq + 8) * FA_QSTR + 8 * kk + tig + 4];
#pragma unroll
            for (int nt = 0; nt < 8; nt++) {
                uint32_t kf[2];
                kf[0] = Ksb[(8 * nt + gid) * FA_KSTR + 8 * kk + tig];
                kf[1] = Ksb[(8 * nt + gid) * FA_KSTR + 8 * kk + tig + 4];
                mma_tf32(c[nt], qa, kf);
            }
        }

        const int k0 = kb * FA_BK;
#pragma unroll
        for (int nt = 0; nt < 8; nt++)
#pragma unroll
            for (int e = 0; e < 4; e++) c[nt][e] *= CEXP;

        if (k0 + 63 > q0 + 16 * w) {
            const int r0g = q0 + rq;
#pragma unroll
            for (int nt = 0; nt < 8; nt++) {
                const int cb = k0 + 8 * nt + 2 * tig;
                if (cb > r0g) c[nt][0] = -1e30f;
                if (cb + 1 > r0g) c[nt][1] = -1e30f;
                if (cb > r0g + 8) c[nt][2] = -1e30f;
                if (cb + 1 > r0g + 8) c[nt][3] = -1e30f;
            }
        }

        float mx0 = -1e30f, mx1 = -1e30f;
#pragma unroll
        for (int nt = 0; nt < 8; nt++) {
            mx0 = fmaxf(mx0, fmaxf(c[nt][0], c[nt][1]));
            mx1 = fmaxf(mx1, fmaxf(c[nt][2], c[nt][3]));
        }
        mx0 = fmaxf(mx0, __shfl_xor_sync(0xffffffffu, mx0, 1));
        mx0 = fmaxf(mx0, __shfl_xor_sync(0xffffffffu, mx0, 2));
        mx1 = fmaxf(mx1, __shfl_xor_sync(0xffffffffu, mx1, 1));
        mx1 = fmaxf(mx1, __shfl_xor_sync(0xffffffffu, mx1, 2));

        const float mn0 = fmaxf(fmaxf(m0, mx0), -1000.0f);
        const float mn1 = fmaxf(fmaxf(m1, mx1), -1000.0f);
        const float corr0 = ex2(m0 - mn0);
        const float corr1 = ex2(m1 - mn1);

        float rs0 = 0.0f, rs1 = 0.0f;
#pragma unroll
        for (int nt = 0; nt < 8; nt++) {
            c[nt][0] = ex2(c[nt][0] - mn0);
            c[nt][1] = ex2(c[nt][1] - mn0);
            c[nt][2] = ex2(c[nt][2] - mn1);
            c[nt][3] = ex2(c[nt][3] - mn1);
            rs0 += c[nt][0] + c[nt][1];
            rs1 += c[nt][2] + c[nt][3];
        }
        rs0 += __shfl_xor_sync(0xffffffffu, rs0, 1);
        rs0 += __shfl_xor_sync(0xffffffffu, rs0, 2);
        rs1 += __shfl_xor_sync(0xffffffffu, rs1, 1);
        rs1 += __shfl_xor_sync(0xffffffffu, rs1, 2);

        l0 = l0 * corr0 + rs0;
        l1 = l1 * corr1 + rs1;
        m0 = mn0;
        m1 = mn1;

#pragma unroll
        for (int nt = 0; nt < 8; nt++) {
            o[nt][0] *= corr0;
            o[nt][1] *= corr0;
            o[nt][2] *= corr1;
            o[nt][3] *= corr1;
        }

        const int srcA = (lane & 28) | (tig >> 1);
        const int srcB = srcA + 2;
        const bool odd = (tig & 1) != 0;
#pragma unroll
        for (int j = 0; j < 8; j++) {
            const float v00 = __shfl_sync(0xffffffffu, c[j][0], srcA);
            const float v01 = __shfl_sync(0xffffffffu, c[j][1], srcA);
            const float v10 = __shfl_sync(0xffffffffu, c[j][0], srcB);
            const float v11 = __shfl_sync(0xffffffffu, c[j][1], srcB);
            const float v20 = __shfl_sync(0xffffffffu, c[j][2], srcA);
            const float v21 = __shfl_sync(0xffffffffu, c[j][3], srcA);
            const float v30 = __shfl_sync(0xffffffffu, c[j][2], srcB);
            const float v31 = __shfl_sync(0xffffffffu, c[j][3], srcB);
            uint32_t pa[4];
            pa[0] = f2tf32(odd ? v01 : v00);
            pa[2] = f2tf32(odd ? v11 : v10);
            pa[1] = f2tf32(odd ? v21 : v20);
            pa[3] = f2tf32(odd ? v31 : v30);
#pragma unroll
            for (int nt = 0; nt < 8; nt++) {
                uint32_t vf[2];
                vf[0] = Vsb[(8 * j + tig) * FA_VSTR + 8 * nt + gid];
                vf[1] = Vsb[(8 * j + tig + 4) * FA_VSTR + 8 * nt + gid];
                mma_tf32(o[nt], pa, vf);
            }
        }
        __syncthreads();
    }

    // normalize + write ctx tf32-rounded in (B, L, D) layout (feeds Wo mma raw)
    const float inv0 = 1.0f / l0;
    const float inv1 = 1.0f / l1;
    const int b = bh >> 4;
    const int h = bh & 15;
    const int r0 = q0 + rq;
#pragma unroll
    for (int nt = 0; nt < 8; nt++) {
        const int col = h * HDIM + 8 * nt + 2 * tig;
        *reinterpret_cast<uint2*>(ctx + ((size_t)(b * SEQ + r0) * DMODEL) + col) =
            make_uint2(f2tf32(o[nt][0] * inv0), f2tf32(o[nt][1] * inv0));
        *reinterpret_cast<uint2*>(ctx + ((size_t)(b * SEQ + r0 + 8) * DMODEL) + col) =
            make_uint2(f2tf32(o[nt][2] * inv1), f2tf32(o[nt][3] * inv1));
    }
}

// ---------------------------------------------------------------------------
// Launch
// ---------------------------------------------------------------------------
static float* sym_addr(const void* symbol) {
    void* p = nullptr;
    cudaGetSymbolAddress(&p, symbol);
    return reinterpret_cast<float*>(p);
}

extern "C" void kernel_launch(void* const* d_in, const int* in_sizes, int n_in,
                              void* d_out, int out_size) {
    const float* x  = (const float*)d_in[0];
    const float* Wq = (const float*)d_in[1];
    const float* Wk = (const float*)d_in[2];
    const float* Wv = (const float*)d_in[3];
    const float* Wo = (const float*)d_in[4];
    float* out = (float*)d_out;

    float* q   = sym_addr(g_q);
    float* k   = sym_addr(g_k);
    float* v   = sym_addr(g_v);
    float* ctx = sym_addr(g_ctx);
    float* xr  = sym_addr(g_xr);
    float* wq  = sym_addr(g_wq);
    float* wk  = sym_addr(g_wk);
    float* wv  = sym_addr(g_wv);
    float* wo  = sym_addr(g_wo);

    cudaFuncSetAttribute(gemm_mma<1>, cudaFuncAttributeMaxDynamicSharedMemorySize, GSMEM_BYTES);
    cudaFuncSetAttribute(gemm_mma<0>, cudaFuncAttributeMaxDynamicSharedMemorySize, GSMEM_BYTES);
    cudaFuncSetAttribute(flash_mma, cudaFuncAttributeMaxDynamicSharedMemorySize, FA_SMEM_BYTES);

    // tf32 pre-round (rna) of all GEMM inputs
    round_tf32<<<512, 256>>>(x, xr, MTOT * DMODEL / 4);
    round_tf32<<<256, 256>>>(Wq, wq, DMODEL * DMODEL / 4);
    round_tf32<<<256, 256>>>(Wk, wk, DMODEL * DMODEL / 4);
    round_tf32<<<256, 256>>>(Wv, wv, DMODEL * DMODEL / 4);
    round_tf32<<<256, 256>>>(Wo, wo, DMODEL * DMODEL / 4);

    // fused QKV projection: N = 3072
    dim3 gqkv(3 * DMODEL / 128, MTOT / 128);   // (24, 32)
    gemm_mma<1><<<gqkv, 256, GSMEM_BYTES>>>(xr, wq, wk, wv, q, k, v);

    dim3 ga(SEQ / FA_BQ, BATCH * NHEAD);       // (16, 32)
    flash_mma<<<ga, 256, FA_SMEM_BYTES>>>(q, k, v, ctx);

    dim3 go(DMODEL / 128, MTOT / 128);         // (8, 32)
    gemm_mma<0><<<go, 256, GSMEM_BYTES>>>(ctx, wo, nullptr, nullptr, out, nullptr, nullptr);
}